// round 16
// baseline (speedup 1.0000x reference)
#include <cuda_runtime.h>
#include <math.h>
#include <stdint.h>

#define BB 64
#define CIN 64
#define T0 4096
#define HH 64
#define H 128
#define T1 2048
#define T2 1024
#define RH 64
#define DD 64
#define KCB 512
#define NN (BB*T2)

__device__ float g_h1[(size_t)BB*HH*T1];
__device__ float g_h2[(size_t)BB*H*T2];
__device__ float g_h3[(size_t)BB*H*T2];
__device__ float g_WcT[H*DD];
__device__ float g_bc[DD];
__device__ float g_cnorm[KCB];
__device__ int   g_hist[KCB];
__device__ float g_losssum;

__device__ __forceinline__ void cpa16(void* d, const float* s, bool ok) {
    uint32_t da = (uint32_t)__cvta_generic_to_shared(d);
    asm volatile("cp.async.cg.shared.global [%0], [%1], 16, %2;" :: "r"(da), "l"(s), "r"(ok?16:0));
}
__device__ __forceinline__ void cpa4(void* d, const float* s) {
    uint32_t da = (uint32_t)__cvta_generic_to_shared(d);
    asm volatile("cp.async.ca.shared.global [%0], [%1], 4;" :: "r"(da), "l"(s));
}
__device__ __forceinline__ void cp_commit() { asm volatile("cp.async.commit_group;"); }
__device__ __forceinline__ void cp_wait0()  { asm volatile("cp.async.wait_group 0;"); }

__global__ void precompute_k(const float* __restrict__ wpq, const float* __restrict__ w_out,
                             const float* __restrict__ b_out, const float* __restrict__ bpq,
                             const float* __restrict__ cb)
{
    const int bid = blockIdx.x, tid = threadIdx.x;
    if (bid < 64) {
        __shared__ float wrow[64];
        if (tid < 64) wrow[tid] = wpq[bid*DD + tid];
        __syncthreads();
        float s = 0.f;
        #pragma unroll
        for (int d = 0; d < DD; d++) s = fmaf(wrow[d], w_out[d*H + tid], s);
        g_WcT[tid*DD + bid] = s;
    } else if (bid == 64) {
        if (tid < DD) {
            float s = bpq[tid];
            #pragma unroll
            for (int d = 0; d < DD; d++) s = fmaf(wpq[tid*DD + d], b_out[d], s);
            g_bc[tid] = s;
        }
        if (tid == 0) g_losssum = 0.f;
    } else {
        for (int k = tid; k < KCB; k += 128) {
            float s = 0.f;
            #pragma unroll
            for (int d = 0; d < DD; d++) { float c = cb[k*DD + d]; s = fmaf(c, c, s); }
            g_cnorm[k] = s; g_hist[k] = 0;
        }
    }
}

// ---- K=4 S=2 conv + bias + relu (R15-proven) ----
#define S2_WC (16*4*64)
#define S2_XC (16*264)
__global__ void __launch_bounds__(256,3) convS2_k(
    const float* __restrict__ in, const float* __restrict__ w,
    const float* __restrict__ bias, float* __restrict__ out,
    int Cin, int Tin, int Cout, int Tout)
{
    extern __shared__ float sm[];
    float* swb = sm; float* sxb = sm + 2*S2_WC;
    const int tid = threadIdx.x, tslot = tid&15, cslot = tid>>4;
    const int t0 = blockIdx.x*128, co0 = blockIdx.y*64, b = blockIdx.z;

    float acc[4][8];
    #pragma unroll
    for (int c = 0; c < 4; c++) {
        float bv = bias[co0 + cslot*4 + c];
        #pragma unroll
        for (int j = 0; j < 8; j++) acc[c][j] = bv;
    }
    auto load_chunk = [&](int cc, int buf) {
        float* sx = sxb + buf*S2_XC;
        for (int idx = tid; idx < 16*66; idx += 256) {
            int ci = idx/66, q = idx - ci*66;
            int gb = 2*t0 - 4 + 4*q;
            bool ok = (gb >= 0) && (gb + 4 <= Tin);
            cpa16(&sx[ci*264 + 4*q], in + ((size_t)b*Cin + cc + ci)*Tin + (ok?gb:0), ok);
        }
        float* sw = swb + buf*S2_WC;
        for (int idx = tid; idx < 16*4*64; idx += 256) {
            int co = idx&63, r = idx>>6, ci = r>>2, k = r&3;
            cpa4(&sw[idx], &w[((size_t)(co0+co)*Cin + cc + ci)*4 + k]);
        }
    };
    const int nch = Cin>>4;
    load_chunk(0,0); cp_commit();
    for (int c = 0; c < nch; c++) {
        cp_wait0(); __syncthreads();
        if (c + 1 < nch) { load_chunk((c+1)<<4, (c+1)&1); cp_commit(); }
        const float* sx = sxb + (c&1)*S2_XC;
        const float* sw = swb + (c&1)*S2_WC;
        #pragma unroll 2
        for (int ci = 0; ci < 16; ci++) {
            float x[24];
            const float* xr = &sx[ci*264 + tslot*16];
            #pragma unroll
            for (int q = 0; q < 6; q++) { float4 v = *(const float4*)(xr+4*q); x[4*q]=v.x; x[4*q+1]=v.y; x[4*q+2]=v.z; x[4*q+3]=v.w; }
            float wv[4][4];
            #pragma unroll
            for (int k = 0; k < 4; k++) {
                float4 v = *(const float4*)&sw[(ci*4+k)*64 + cslot*4];
                wv[k][0]=v.x; wv[k][1]=v.y; wv[k][2]=v.z; wv[k][3]=v.w;
            }
            #pragma unroll
            for (int c4 = 0; c4 < 4; c4++)
                #pragma unroll
                for (int j = 0; j < 8; j++)
                    #pragma unroll
                    for (int k = 0; k < 4; k++)
                        acc[c4][j] = fmaf(x[2*j+3+k], wv[k][c4], acc[c4][j]);
        }
    }
    #pragma unroll
    for (int c = 0; c < 4; c++) {
        float4* op = (float4*)(out + ((size_t)b*Cout + co0 + cslot*4 + c)*Tout + t0 + tslot*8);
        op[0] = make_float4(fmaxf(acc[c][0],0.f), fmaxf(acc[c][1],0.f), fmaxf(acc[c][2],0.f), fmaxf(acc[c][3],0.f));
        op[1] = make_float4(fmaxf(acc[c][4],0.f), fmaxf(acc[c][5],0.f), fmaxf(acc[c][6],0.f), fmaxf(acc[c][7],0.f));
    }
}

// ---- conv3 v2: lane-remapped 4co x 16t; conflict-free padded x; Cout=128; 2-stage ----
// x smem: [ci][8 tslot][28] (24 used), base g = t0 + tslot*16 - 4. w smem: [ci*3+k][128 co].
#define C3_WC (16*3*128)   // 6144
#define C3_XC (16*224)     // 3584
template<bool RELU_IN, bool RELU_OUT, bool HAS_BIAS>
__global__ void __launch_bounds__(256,2) convK3_k(
    const float* __restrict__ in, const float* __restrict__ w,
    const float* __restrict__ bias, float* __restrict__ out)
{
    extern __shared__ float sm[];
    float* swb = sm; float* sxb = sm + 2*C3_WC;
    const int tid = threadIdx.x, tslot = tid&7, cslot = tid>>3;
    const int t0 = blockIdx.x*128, b = blockIdx.z;
    const int Cin = H, Cout = H;

    float acc[4][16];
    #pragma unroll
    for (int c = 0; c < 4; c++) {
        float bv = HAS_BIAS ? bias[cslot*4 + c] : 0.f;
        #pragma unroll
        for (int j = 0; j < 16; j++) acc[c][j] = bv;
    }
    auto load_chunk = [&](int cc, int buf) {
        float* sx = sxb + buf*C3_XC;
        for (int idx = tid; idx < 16*48; idx += 256) {     // ci x (8 tslot x 6 q)
            int ci = idx/48, rem = idx - ci*48, s = rem/6, q = rem - s*6;
            int gb = t0 + s*16 - 4 + 4*q;
            bool ok = (gb >= 0) && (gb + 4 <= T2);
            cpa16(&sx[ci*224 + s*28 + 4*q], in + ((size_t)b*Cin + cc + ci)*T2 + (ok?gb:0), ok);
        }
        float* sw = swb + buf*C3_WC;
        for (int idx = tid; idx < 16*3*128; idx += 256) {
            int co = idx&127, r = idx>>7, ci = r/3, k = r - ci*3;
            cpa4(&sw[idx], &w[((size_t)co*Cin + cc + ci)*3 + k]);
        }
    };
    load_chunk(0,0); cp_commit();
    for (int c = 0; c < 8; c++) {
        cp_wait0(); __syncthreads();
        if (c + 1 < 8) { load_chunk((c+1)<<4, (c+1)&1); cp_commit(); }
        const float* sx = sxb + (c&1)*C3_XC;
        const float* sw = swb + (c&1)*C3_WC;
        #pragma unroll 1
        for (int ci = 0; ci < 16; ci++) {
            float x[24];
            const float* xr = &sx[ci*224 + tslot*28];
            #pragma unroll
            for (int q = 0; q < 6; q++) { float4 v = *(const float4*)(xr+4*q); x[4*q]=v.x; x[4*q+1]=v.y; x[4*q+2]=v.z; x[4*q+3]=v.w; }
            if (RELU_IN) {
                #pragma unroll
                for (int i = 0; i < 24; i++) x[i] = fmaxf(x[i], 0.f);
            }
            #pragma unroll
            for (int k = 0; k < 3; k++) {
                float4 wv = *(const float4*)&sw[(ci*3+k)*128 + cslot*4];
                float wc[4] = {wv.x, wv.y, wv.z, wv.w};
                #pragma unroll
                for (int c4 = 0; c4 < 4; c4++)
                    #pragma unroll
                    for (int j = 0; j < 16; j++)
                        acc[c4][j] = fmaf(x[j+3+k], wc[c4], acc[c4][j]);
            }
        }
    }
    #pragma unroll
    for (int c = 0; c < 4; c++) {
        float* op = out + ((size_t)b*Cout + cslot*4 + c)*T2 + t0 + tslot*16;
        #pragma unroll
        for (int q = 0; q < 4; q++) {
            float v0 = acc[c][4*q], v1 = acc[c][4*q+1], v2 = acc[c][4*q+2], v3 = acc[c][4*q+3];
            if (RELU_OUT) { v0=fmaxf(v0,0.f); v1=fmaxf(v1,0.f); v2=fmaxf(v2,0.f); v3=fmaxf(v3,0.f); }
            ((float4*)op)[q] = make_float4(v0, v1, v2, v3);
        }
    }
}

// ---- fused residual block: phase B lane-remapped 2mid x 16t; phase C unchanged ----
#define RN_STA (64*132)
#define RB2_WC (16*3*64)     // 3072
#define RB2_XC (16*224)      // 3584
#define RB2_STG (RB2_WC + RB2_XC)
__global__ void __launch_bounds__(256) resblock_k(
    const float* __restrict__ in, const float* __restrict__ wa,
    const float* __restrict__ wb, float* __restrict__ out)
{
    extern __shared__ float s[];
    float* sta = s;                  // [64 mid][132]
    float* pb  = s + RN_STA;         // 2 stages (W | X); later wb alias
    const int tid = threadIdx.x;
    const int t0 = blockIdx.x*128, b = blockIdx.z;

    auto load_chunk = [&](int cc, int buf) {
        float* sw = pb + buf*RB2_STG;
        float* sx = sw + RB2_WC;
        for (int idx = tid; idx < 16*48; idx += 256) {
            int ci = idx/48, rem = idx - ci*48, sl = rem/6, q = rem - sl*6;
            int gb = t0 + sl*16 - 4 + 4*q;
            bool ok = (gb >= 0) && (gb + 4 <= T2);
            cpa16(&sx[ci*224 + sl*28 + 4*q], in + ((size_t)b*H + cc + ci)*T2 + (ok?gb:0), ok);
        }
        for (int idx = tid; idx < 16*3*64; idx += 256) {
            int mid = idx&63, r = idx>>6, ci = r/3, k = r - ci*3;
            cpa4(&sw[idx], &wa[((size_t)mid*H + cc + ci)*3 + k]);
        }
    };

    // phase B: mid = relu(conv3(relu(in))); thread = 2 mid x 16 t
    {
        const int tslot = tid&7, cslot = tid>>3;   // mid = cslot*2 + c
        float acc[2][16];
        #pragma unroll
        for (int c = 0; c < 2; c++)
            #pragma unroll
            for (int j = 0; j < 16; j++) acc[c][j] = 0.f;
        load_chunk(0,0); cp_commit();
        for (int ch = 0; ch < 8; ch++) {
            cp_wait0(); __syncthreads();
            if (ch + 1 < 8) { load_chunk((ch+1)*16, (ch+1)&1); cp_commit(); }
            const float* sw = pb + (ch&1)*RB2_STG;
            const float* sx = sw + RB2_WC;
            #pragma unroll 1
            for (int ci = 0; ci < 16; ci++) {
                float x[24];
                const float* xr = &sx[ci*224 + tslot*28];
                #pragma unroll
                for (int q = 0; q < 6; q++) { float4 v = *(const float4*)(xr+4*q); x[4*q]=v.x; x[4*q+1]=v.y; x[4*q+2]=v.z; x[4*q+3]=v.w; }
                #pragma unroll
                for (int i = 0; i < 24; i++) x[i] = fmaxf(x[i], 0.f);
                #pragma unroll
                for (int k = 0; k < 3; k++) {
                    float2 wv = *(const float2*)&sw[(ci*3+k)*64 + cslot*2];
                    #pragma unroll
                    for (int j = 0; j < 16; j++) {
                        acc[0][j] = fmaf(x[j+3+k], wv.x, acc[0][j]);
                        acc[1][j] = fmaf(x[j+3+k], wv.y, acc[1][j]);
                    }
                }
            }
        }
        __syncthreads();
        #pragma unroll
        for (int c = 0; c < 2; c++) {
            float* d = &sta[(cslot*2 + c)*132 + tslot*16];
            #pragma unroll
            for (int q = 0; q < 4; q++)
                ((float4*)d)[q] = make_float4(fmaxf(acc[c][4*q],0.f), fmaxf(acc[c][4*q+1],0.f),
                                              fmaxf(acc[c][4*q+2],0.f), fmaxf(acc[c][4*q+3],0.f));
        }
    }
    __syncthreads();

    // wb -> alias over pb: [mid][132 co]
    float* wbs = pb;
    for (int idx = tid; idx < H*RH; idx += 256) {
        int co = idx>>6, mid = idx&63;
        wbs[mid*132 + co] = wb[idx];
    }
    __syncthreads();

    // phase C: out = in + wb @ mid; thread = 4 co x 8 t, two co-halves
    {
        const int tslot = tid&15, cslot = tid>>4;
        #pragma unroll 1
        for (int coh = 0; coh < 2; coh++) {
            float acc[4][8];
            #pragma unroll
            for (int c = 0; c < 4; c++)
                #pragma unroll
                for (int j = 0; j < 8; j++) acc[c][j] = 0.f;
            #pragma unroll 2
            for (int mid = 0; mid < RH; mid++) {
                float x[8];
                const float* xr = &sta[mid*132 + tslot*8];
                { float4 v = *(const float4*)(xr);   x[0]=v.x; x[1]=v.y; x[2]=v.z; x[3]=v.w; }
                { float4 v = *(const float4*)(xr+4); x[4]=v.x; x[5]=v.y; x[6]=v.z; x[7]=v.w; }
                float4 wv = *(const float4*)&wbs[mid*132 + coh*64 + cslot*4];
                float wc[4] = {wv.x, wv.y, wv.z, wv.w};
                #pragma unroll
                for (int c = 0; c < 4; c++)
                    #pragma unroll
                    for (int j = 0; j < 8; j++) acc[c][j] = fmaf(x[j], wc[c], acc[c][j]);
            }
            #pragma unroll
            for (int c = 0; c < 4; c++) {
                int co = coh*64 + cslot*4 + c;
                const float4* ip = (const float4*)(in + ((size_t)b*H + co)*T2 + t0 + tslot*8);
                float4 r0 = ip[0], r1 = ip[1];
                float4* op = (float4*)(out + ((size_t)b*H + co)*T2 + t0 + tslot*8);
                op[0] = make_float4(r0.x+acc[c][0], r0.y+acc[c][1], r0.z+acc[c][2], r0.w+acc[c][3]);
                op[1] = make_float4(r1.x+acc[c][4], r1.y+acc[c][5], r1.z+acc[c][6], r1.w+acc[c][7]);
            }
        }
    }
}

// ---- fused relu + Wc + transpose -> z_e (R15-proven) ----
#define Z_SH (128*136)
#define Z_SW (128*64)
__global__ void __launch_bounds__(256) zfused_k(const float* __restrict__ h, float* __restrict__ ze)
{
    extern __shared__ float s[];
    float* sh = s; float* sw = s + Z_SH;
    const int tid = threadIdx.x, tslot = tid&15, cslot = tid>>4;
    const int t0 = blockIdx.x*128, b = blockIdx.z;

    for (int idx = tid; idx < 128*128; idx += 256) {
        int ci = idx>>7, t = idx&127;
        sh[ci*136 + t] = fmaxf(h[((size_t)b*H + ci)*T2 + t0 + t], 0.f);
    }
    for (int i = tid; i < (H*DD)/4; i += 256) ((float4*)sw)[i] = ((const float4*)g_WcT)[i];
    __syncthreads();

    float acc[4][8];
    #pragma unroll
    for (int c = 0; c < 4; c++) {
        float bv = g_bc[cslot*4 + c];
        #pragma unroll
        for (int j = 0; j < 8; j++) acc[c][j] = bv;
    }
    #pragma unroll 2
    for (int ch = 0; ch < H; ch++) {
        float x[8];
        const float* xr = &sh[ch*136 + tslot*8];
        { float4 v = *(const float4*)(xr);   x[0]=v.x; x[1]=v.y; x[2]=v.z; x[3]=v.w; }
        { float4 v = *(const float4*)(xr+4); x[4]=v.x; x[5]=v.y; x[6]=v.z; x[7]=v.w; }
        float4 wv = *(const float4*)&sw[ch*64 + cslot*4];
        float wc[4] = {wv.x, wv.y, wv.z, wv.w};
        #pragma unroll
        for (int c = 0; c < 4; c++)
            #pragma unroll
            for (int j = 0; j < 8; j++) acc[c][j] = fmaf(x[j], wc[c], acc[c][j]);
    }
    #pragma unroll
    for (int j = 0; j < 8; j++) {
        size_t n = (size_t)b*T2 + t0 + tslot*8 + j;
        float2* op = (float2*)(ze + n*DD + cslot*4);
        op[0] = make_float2(acc[0][j], acc[1][j]);
        op[1] = make_float2(acc[2][j], acc[3][j]);
    }
}

// ---- VQ distance-GEMM (R15-proven) ----
#define VQ_SZ (64*136)
#define VQ_SC (64*136)
__global__ void __launch_bounds__(256) vqgemm_k(
    const float* __restrict__ ze, const float* __restrict__ cb,
    float* __restrict__ zq, float* __restrict__ enc, float* __restrict__ idxout)
{
    extern __shared__ float s[];
    float* szeT = s; float* scb = s + VQ_SZ; float* scn = scb + VQ_SC;
    int* sbk = (int*)(scn + KCB);
    const int tid = threadIdx.x, n0 = blockIdx.x*128, nslot = tid>>4, kslot = tid&15;

    for (int idx = tid; idx < 128*DD; idx += 256) {
        int n = idx>>6, d = idx&63;
        szeT[d*136 + n] = ze[(size_t)(n0+n)*DD + d];
    }
    for (int k = tid; k < KCB; k += 256) scn[k] = g_cnorm[k];
    __syncthreads();

    float best[8]; int bk[8];
    #pragma unroll
    for (int i = 0; i < 8; i++) { best[i] = 3.4e38f; bk[i] = 0; }

    for (int kc = 0; kc < KCB; kc += 128) {
        for (int idx = tid; idx < 128*DD; idx += 256) {
            int kk = idx>>6, d = idx&63;
            scb[d*136 + kk] = cb[(size_t)(kc+kk)*DD + d];
        }
        __syncthreads();
        float acc[8][8];
        #pragma unroll
        for (int i = 0; i < 8; i++)
            #pragma unroll
            for (int j = 0; j < 8; j++) acc[i][j] = 0.f;
        #pragma unroll 2
        for (int d = 0; d < DD; d++) {
            float fz[8], fc[8];
            const float* zr = &szeT[d*136 + nslot*8];
            { float4 v = *(const float4*)(zr);   fz[0]=v.x; fz[1]=v.y; fz[2]=v.z; fz[3]=v.w; }
            { float4 v = *(const float4*)(zr+4); fz[4]=v.x; fz[5]=v.y; fz[6]=v.z; fz[7]=v.w; }
            const float* cr = &scb[d*136 + kslot*8];
            { float4 v = *(const float4*)(cr);   fc[0]=v.x; fc[1]=v.y; fc[2]=v.z; fc[3]=v.w; }
            { float4 v = *(const float4*)(cr+4); fc[4]=v.x; fc[5]=v.y; fc[6]=v.z; fc[7]=v.w; }
            #pragma unroll
            for (int i = 0; i < 8; i++)
                #pragma unroll
                for (int j = 0; j < 8; j++) acc[i][j] = fmaf(fz[i], fc[j], acc[i][j]);
        }
        #pragma unroll
        for (int j = 0; j < 8; j++) {
            int kg = kc + kslot*8 + j;
            float cn = scn[kg];
            #pragma unroll
            for (int i = 0; i < 8; i++) {
                float dist = cn - 2.f*acc[i][j];
                if (dist < best[i]) { best[i] = dist; bk[i] = kg; }
            }
        }
        __syncthreads();
    }
    #pragma unroll
    for (int off = 8; off > 0; off >>= 1) {
        #pragma unroll
        for (int i = 0; i < 8; i++) {
            float ob = __shfl_down_sync(0xffffffffu, best[i], off, 16);
            int ok = __shfl_down_sync(0xffffffffu, bk[i], off, 16);
            if (ob < best[i] || (ob == best[i] && ok < bk[i])) { best[i] = ob; bk[i] = ok; }
        }
    }
    if (kslot == 0)
        #pragma unroll
        for (int i = 0; i < 8; i++) sbk[nslot*8 + i] = bk[i];
    __syncthreads();

    float part = 0.f;
    for (int idx = tid; idx < 128*DD; idx += 256) {
        int nl = idx>>6, d = idx&63;
        int kk = sbk[nl];
        float c = cb[(size_t)kk*DD + d];
        float f = szeT[d*136 + nl];
        zq[(size_t)(n0+nl)*DD + d] = c;
        float df = c - f;
        part = fmaf(df, df, part);
    }
    const float2 z2 = make_float2(0.f, 0.f);
    for (int r = 0; r < 128; r++) ((float2*)(enc + (size_t)(n0+r)*KCB))[tid] = z2;
    __syncthreads();
    if (tid < 128) {
        int kk = sbk[tid];
        idxout[n0 + tid] = (float)kk;
        enc[(size_t)(n0+tid)*KCB + kk] = 1.f;
        atomicAdd(&g_hist[kk], 1);
    }
    #pragma unroll
    for (int o = 16; o > 0; o >>= 1) part += __shfl_down_sync(0xffffffffu, part, o);
    __shared__ float wsum[8];
    if ((tid&31) == 0) wsum[tid>>5] = part;
    __syncthreads();
    if (tid < 8) {
        float v = wsum[tid];
        #pragma unroll
        for (int o = 4; o > 0; o >>= 1) v += __shfl_down_sync(0xffu, v, o);
        if (tid == 0) atomicAdd(&g_losssum, v);
    }
}

__global__ void fin_k(float* __restrict__ loss_out, float* __restrict__ perp_out)
{
    __shared__ float red[512];
    const int k = threadIdx.x;
    float p = (float)g_hist[k]*(1.0f/(float)NN);
    red[k] = p*logf(p + 1e-10f);
    __syncthreads();
    for (int s2 = 256; s2 > 0; s2 >>= 1) { if (k < s2) red[k] += red[k + s2]; __syncthreads(); }
    if (k == 0) {
        perp_out[0] = expf(-red[0]);
        loss_out[0] = 1.25f*g_losssum/(float)((size_t)NN*DD);
    }
}

extern "C" void kernel_launch(void* const* d_in, const int* in_sizes, int n_in,
                              void* d_out, int out_size)
{
    const float* x     = (const float*)d_in[0];
    const float* w1    = (const float*)d_in[1];
    const float* b1    = (const float*)d_in[2];
    const float* w2    = (const float*)d_in[3];
    const float* b2    = (const float*)d_in[4];
    const float* w3    = (const float*)d_in[5];
    const float* b3    = (const float*)d_in[6];
    const float* r0w1  = (const float*)d_in[7];
    const float* r0w2  = (const float*)d_in[8];
    const float* r1w1  = (const float*)d_in[9];
    const float* r1w2  = (const float*)d_in[10];
    const float* w_out = (const float*)d_in[11];
    const float* b_out = (const float*)d_in[12];
    const float* wpq   = (const float*)d_in[13];
    const float* bpq   = (const float*)d_in[14];
    const float* cb    = (const float*)d_in[15];

    float* outp = (float*)d_out;
    const size_t NZ = (size_t)NN*DD;
    float* o_loss = outp;
    float* o_zq   = outp + 1;
    float* o_perp = outp + 1 + NZ;
    float* o_ze   = outp + 2 + NZ;
    float* o_enc  = outp + 2 + 2*NZ;
    float* o_idx  = outp + 2 + 2*NZ + (size_t)NN*KCB;

    auto* kConv3 = convK3_k<false, false, true>;

    const int smem_S2 = 2*(S2_WC + S2_XC)*4;          // 66,560
    const int smem_C3 = 2*(C3_WC + C3_XC)*4;          // 77,824
    const int smem_RB = (RN_STA + 2*RB2_STG)*4;       // 87,040
    const int z_smem  = (Z_SH + Z_SW)*4;              // 102,400
    const int vq_smem = (VQ_SZ + VQ_SC + KCB)*4 + 128*4;

    static int attr_done = 0;
    if (!attr_done) {
        cudaFuncSetAttribute(convS2_k,   cudaFuncAttributeMaxDynamicSharedMemorySize, smem_S2);
        cudaFuncSetAttribute(kConv3,     cudaFuncAttributeMaxDynamicSharedMemorySize, smem_C3);
        cudaFuncSetAttribute(resblock_k, cudaFuncAttributeMaxDynamicSharedMemorySize, smem_RB);
        cudaFuncSetAttribute(zfused_k,   cudaFuncAttributeMaxDynamicSharedMemorySize, z_smem);
        cudaFuncSetAttribute(vqgemm_k,   cudaFuncAttributeMaxDynamicSharedMemorySize, vq_smem);
        attr_done = 1;
    }

    precompute_k<<<66, 128>>>(wpq, w_out, b_out, bpq, cb);

    convS2_k<<<dim3(16, 1, BB), 256, smem_S2>>>(x,    w1, b1, g_h1, CIN, T0, HH, T1);
    convS2_k<<<dim3(8,  2, BB), 256, smem_S2>>>(g_h1, w2, b2, g_h2, HH,  T1, H,  T2);
    kConv3<<<dim3(8, 1, BB), 256, smem_C3>>>(g_h2, w3, b3, g_h3);

    resblock_k<<<dim3(8, 1, BB), 256, smem_RB>>>(g_h3, r0w1, r0w2, g_h2);
    resblock_k<<<dim3(8, 1, BB), 256, smem_RB>>>(g_h2, r1w1, r1w2, g_h3);

    zfused_k<<<dim3(8, 1, BB), 256, z_smem>>>(g_h3, o_ze);

    vqgemm_k<<<NN/128, 256, vq_smem>>>(o_ze, cb, o_zq, o_enc, o_idx);

    fin_k<<<1, 512>>>(o_loss, o_perp);
}

// round 17
// speedup vs baseline: 1.2590x; 1.2590x over previous
#include <cuda_runtime.h>
#include <math.h>
#include <stdint.h>

#define BB 64
#define CIN 64
#define T0 4096
#define HH 64
#define H 128
#define T1 2048
#define T2 1024
#define RH 64
#define DD 64
#define KCB 512
#define NN (BB*T2)

__device__ float g_h1[(size_t)BB*HH*T1];
__device__ float g_h2[(size_t)BB*H*T2];
__device__ float g_h3[(size_t)BB*H*T2];
__device__ float g_WcT[H*DD];
__device__ float g_bc[DD];
__device__ float g_cnorm[KCB];
__device__ int   g_hist[KCB];
__device__ float g_losssum;

__device__ __forceinline__ void cpa16(void* d, const float* s, bool ok) {
    uint32_t da = (uint32_t)__cvta_generic_to_shared(d);
    asm volatile("cp.async.cg.shared.global [%0], [%1], 16, %2;" :: "r"(da), "l"(s), "r"(ok?16:0));
}
__device__ __forceinline__ void cpa4(void* d, const float* s) {
    uint32_t da = (uint32_t)__cvta_generic_to_shared(d);
    asm volatile("cp.async.ca.shared.global [%0], [%1], 4;" :: "r"(da), "l"(s));
}
__device__ __forceinline__ void cp_commit() { asm volatile("cp.async.commit_group;"); }
__device__ __forceinline__ void cp_wait0()  { asm volatile("cp.async.wait_group 0;"); }
__device__ __forceinline__ void cp_wait1()  { asm volatile("cp.async.wait_group 1;"); }

__global__ void precompute_k(const float* __restrict__ wpq, const float* __restrict__ w_out,
                             const float* __restrict__ b_out, const float* __restrict__ bpq,
                             const float* __restrict__ cb)
{
    const int bid = blockIdx.x, tid = threadIdx.x;
    if (bid < 64) {
        __shared__ float wrow[64];
        if (tid < 64) wrow[tid] = wpq[bid*DD + tid];
        __syncthreads();
        float s = 0.f;
        #pragma unroll
        for (int d = 0; d < DD; d++) s = fmaf(wrow[d], w_out[d*H + tid], s);
        g_WcT[tid*DD + bid] = s;
    } else if (bid == 64) {
        if (tid < DD) {
            float s = bpq[tid];
            #pragma unroll
            for (int d = 0; d < DD; d++) s = fmaf(wpq[tid*DD + d], b_out[d], s);
            g_bc[tid] = s;
        }
        if (tid == 0) g_losssum = 0.f;
    } else {
        for (int k = tid; k < KCB; k += 128) {
            float s = 0.f;
            #pragma unroll
            for (int d = 0; d < DD; d++) { float c = cb[k*DD + d]; s = fmaf(c, c, s); }
            g_cnorm[k] = s; g_hist[k] = 0;
        }
    }
}

// ---- K=4 S=2 conv + bias + relu (16-ci, 2-stage, 1 bar/chunk, 3 blk) ----
#define S2_WC (16*4*64)
#define S2_XC (16*264)
__global__ void __launch_bounds__(256,3) convS2_k(
    const float* __restrict__ in, const float* __restrict__ w,
    const float* __restrict__ bias, float* __restrict__ out,
    int Cin, int Tin, int Cout, int Tout)
{
    extern __shared__ float sm[];
    float* swb = sm; float* sxb = sm + 2*S2_WC;
    const int tid = threadIdx.x, tslot = tid&15, cslot = tid>>4;
    const int t0 = blockIdx.x*128, co0 = blockIdx.y*64, b = blockIdx.z;

    float acc[4][8];
    #pragma unroll
    for (int c = 0; c < 4; c++) {
        float bv = bias[co0 + cslot*4 + c];
        #pragma unroll
        for (int j = 0; j < 8; j++) acc[c][j] = bv;
    }
    auto load_chunk = [&](int cc, int buf) {
        float* sx = sxb + buf*S2_XC;
        for (int idx = tid; idx < 16*66; idx += 256) {
            int ci = idx/66, q = idx - ci*66;
            int gb = 2*t0 - 4 + 4*q;
            bool ok = (gb >= 0) && (gb + 4 <= Tin);
            cpa16(&sx[ci*264 + 4*q], in + ((size_t)b*Cin + cc + ci)*Tin + (ok?gb:0), ok);
        }
        float* sw = swb + buf*S2_WC;
        for (int idx = tid; idx < 16*4*64; idx += 256) {
            int co = idx&63, r = idx>>6, ci = r>>2, k = r&3;
            cpa4(&sw[idx], &w[((size_t)(co0+co)*Cin + cc + ci)*4 + k]);
        }
    };
    const int nch = Cin>>4;
    load_chunk(0,0); cp_commit();
    for (int c = 0; c < nch; c++) {
        cp_wait0(); __syncthreads();
        if (c + 1 < nch) { load_chunk((c+1)<<4, (c+1)&1); cp_commit(); }
        const float* sx = sxb + (c&1)*S2_XC;
        const float* sw = swb + (c&1)*S2_WC;
        #pragma unroll 2
        for (int ci = 0; ci < 16; ci++) {
            float x[24];
            const float* xr = &sx[ci*264 + tslot*16];
            #pragma unroll
            for (int q = 0; q < 6; q++) { float4 v = *(const float4*)(xr+4*q); x[4*q]=v.x; x[4*q+1]=v.y; x[4*q+2]=v.z; x[4*q+3]=v.w; }
            float wv[4][4];
            #pragma unroll
            for (int k = 0; k < 4; k++) {
                float4 v = *(const float4*)&sw[(ci*4+k)*64 + cslot*4];
                wv[k][0]=v.x; wv[k][1]=v.y; wv[k][2]=v.z; wv[k][3]=v.w;
            }
            #pragma unroll
            for (int c4 = 0; c4 < 4; c4++)
                #pragma unroll
                for (int j = 0; j < 8; j++)
                    #pragma unroll
                    for (int k = 0; k < 4; k++)
                        acc[c4][j] = fmaf(x[2*j+3+k], wv[k][c4], acc[c4][j]);
        }
    }
    #pragma unroll
    for (int c = 0; c < 4; c++) {
        float4* op = (float4*)(out + ((size_t)b*Cout + co0 + cslot*4 + c)*Tout + t0 + tslot*8);
        op[0] = make_float4(fmaxf(acc[c][0],0.f), fmaxf(acc[c][1],0.f), fmaxf(acc[c][2],0.f), fmaxf(acc[c][3],0.f));
        op[1] = make_float4(fmaxf(acc[c][4],0.f), fmaxf(acc[c][5],0.f), fmaxf(acc[c][6],0.f), fmaxf(acc[c][7],0.f));
    }
}

// ---- K=3 S=1 conv (Cin=128, 16-ci, 3-stage, 1 bar/chunk) ----
#define K3_WC (16*3*64)
#define K3_XC (16*136)
template<bool RELU_IN, bool RELU_OUT, bool HAS_BIAS>
__global__ void __launch_bounds__(256,3) convK3_k(
    const float* __restrict__ in, const float* __restrict__ w,
    const float* __restrict__ bias, float* __restrict__ out)
{
    extern __shared__ float sm[];
    float* swb = sm; float* sxb = sm + 3*K3_WC;
    const int tid = threadIdx.x, tslot = tid&15, cslot = tid>>4;
    const int t0 = blockIdx.x*128, co0 = blockIdx.y*64, b = blockIdx.z;
    const int Cout = gridDim.y*64;
    const int Cin = H;

    float acc[4][8];
    #pragma unroll
    for (int c = 0; c < 4; c++) {
        float bv = HAS_BIAS ? bias[co0 + cslot*4 + c] : 0.f;
        #pragma unroll
        for (int j = 0; j < 8; j++) acc[c][j] = bv;
    }
    auto load_chunk = [&](int cc, int buf) {
        float* sx = sxb + buf*K3_XC;
        for (int idx = tid; idx < 16*34; idx += 256) {
            int ci = idx/34, q = idx - ci*34;
            int gb = t0 - 4 + 4*q;
            bool ok = (gb >= 0) && (gb + 4 <= T2);
            cpa16(&sx[ci*136 + 4*q], in + ((size_t)b*Cin + cc + ci)*T2 + (ok?gb:0), ok);
        }
        float* sw = swb + buf*K3_WC;
        for (int idx = tid; idx < 16*3*64; idx += 256) {
            int co = idx&63, r = idx>>6, ci = r/3, k = r - ci*3;
            cpa4(&sw[idx], &w[((size_t)(co0+co)*Cin + cc + ci)*3 + k]);
        }
    };
    const int nch = Cin>>4;
    load_chunk(0,0);  cp_commit();
    load_chunk(16,1); cp_commit();
    #pragma unroll 1
    for (int c = 0; c < nch; c++) {
        if (c == nch-1) cp_wait0(); else cp_wait1();
        __syncthreads();
        if (c + 2 < nch) { load_chunk((c+2)<<4, (c+2)%3); cp_commit(); }
        const float* sx = sxb + (c%3)*K3_XC;
        const float* sw = swb + (c%3)*K3_WC;
        #pragma unroll 2
        for (int ci = 0; ci < 16; ci++) {
            float x[16];
            const float* xr = &sx[ci*136 + tslot*8];
            #pragma unroll
            for (int q = 0; q < 4; q++) { float4 v = *(const float4*)(xr+4*q); x[4*q]=v.x; x[4*q+1]=v.y; x[4*q+2]=v.z; x[4*q+3]=v.w; }
            if (RELU_IN) {
                #pragma unroll
                for (int i = 0; i < 16; i++) x[i] = fmaxf(x[i], 0.f);
            }
            float wv[3][4];
            #pragma unroll
            for (int k = 0; k < 3; k++) {
                float4 v = *(const float4*)&sw[(ci*3+k)*64 + cslot*4];
                wv[k][0]=v.x; wv[k][1]=v.y; wv[k][2]=v.z; wv[k][3]=v.w;
            }
            #pragma unroll
            for (int c4 = 0; c4 < 4; c4++)
                #pragma unroll
                for (int j = 0; j < 8; j++)
                    #pragma unroll
                    for (int k = 0; k < 3; k++)
                        acc[c4][j] = fmaf(x[j+3+k], wv[k][c4], acc[c4][j]);
        }
    }
    #pragma unroll
    for (int c = 0; c < 4; c++) {
        float v[8];
        #pragma unroll
        for (int j = 0; j < 8; j++) v[j] = RELU_OUT ? fmaxf(acc[c][j],0.f) : acc[c][j];
        float4* op = (float4*)(out + ((size_t)b*Cout + co0 + cslot*4 + c)*T2 + t0 + tslot*8);
        op[0] = make_float4(v[0], v[1], v[2], v[3]);
        op[1] = make_float4(v[4], v[5], v[6], v[7]);
    }
}

// ---- fused residual block: 256 thr, mid in smem, 75.8KB ----
#define RN_STA (64*132)
#define RN_WC  (16*3*64)
#define RN_XC  (16*136)
#define RN_STG (RN_WC + RN_XC)
__global__ void __launch_bounds__(256) resblock_k(
    const float* __restrict__ in, const float* __restrict__ wa,
    const float* __restrict__ wb, float* __restrict__ out)
{
    extern __shared__ float s[];
    float* sta = s;
    float* pb  = s + RN_STA;
    const int tid = threadIdx.x, tslot = tid&15, cslot = tid>>4;
    const int t0 = blockIdx.x*128, b = blockIdx.z;

    auto load_chunk = [&](int cc, int buf) {
        float* sw = pb + buf*RN_STG;
        float* sx = sw + RN_WC;
        for (int idx = tid; idx < 16*34; idx += 256) {
            int ci = idx/34, q = idx - ci*34;
            int gb = t0 - 4 + 4*q;
            bool ok = (gb >= 0) && (gb + 4 <= T2);
            cpa16(&sx[ci*136 + 4*q], in + ((size_t)b*H + cc + ci)*T2 + (ok?gb:0), ok);
        }
        for (int idx = tid; idx < 16*3*64; idx += 256) {
            int mid = idx&63, r = idx>>6, ci = r/3, k = r - ci*3;
            cpa4(&sw[idx], &wa[((size_t)mid*H + cc + ci)*3 + k]);
        }
    };

    // phase B: thread = 4 mid x 8 t
    {
        float acc[4][8];
        #pragma unroll
        for (int c = 0; c < 4; c++)
            #pragma unroll
            for (int j = 0; j < 8; j++) acc[c][j] = 0.f;
        load_chunk(0,0); cp_commit();
        for (int ch = 0; ch < 8; ch++) {
            cp_wait0(); __syncthreads();
            if (ch + 1 < 8) { load_chunk((ch+1)*16, (ch+1)&1); cp_commit(); }
            const float* sw = pb + (ch&1)*RN_STG;
            const float* sx = sw + RN_WC;
            #pragma unroll 2
            for (int ci = 0; ci < 16; ci++) {
                float x[16];
                const float* xr = &sx[ci*136 + tslot*8];
                #pragma unroll
                for (int q = 0; q < 4; q++) { float4 v = *(const float4*)(xr+4*q); x[4*q]=v.x; x[4*q+1]=v.y; x[4*q+2]=v.z; x[4*q+3]=v.w; }
                #pragma unroll
                for (int i = 0; i < 16; i++) x[i] = fmaxf(x[i], 0.f);
                float wv[3][4];
                #pragma unroll
                for (int k = 0; k < 3; k++) {
                    float4 v = *(const float4*)&sw[(ci*3+k)*64 + cslot*4];
                    wv[k][0]=v.x; wv[k][1]=v.y; wv[k][2]=v.z; wv[k][3]=v.w;
                }
                #pragma unroll
                for (int c4 = 0; c4 < 4; c4++)
                    #pragma unroll
                    for (int j = 0; j < 8; j++)
                        #pragma unroll
                        for (int k = 0; k < 3; k++)
                            acc[c4][j] = fmaf(x[j+3+k], wv[k][c4], acc[c4][j]);
            }
        }
        __syncthreads();
        #pragma unroll
        for (int c = 0; c < 4; c++) {
            float* d = &sta[(cslot*4 + c)*132 + tslot*8];
            #pragma unroll
            for (int jp = 0; jp < 4; jp++)
                *(float2*)(d + 2*jp) = make_float2(fmaxf(acc[c][2*jp],0.f), fmaxf(acc[c][2*jp+1],0.f));
        }
    }
    __syncthreads();

    float* wbs = pb;
    for (int idx = tid; idx < H*RH; idx += 256) {
        int co = idx>>6, mid = idx&63;
        wbs[mid*132 + co] = wb[idx];
    }
    __syncthreads();

    // phase C: two co-halves, thread = 4 co x 8 t each
    #pragma unroll 1
    for (int coh = 0; coh < 2; coh++) {
        float acc[4][8];
        #pragma unroll
        for (int c = 0; c < 4; c++)
            #pragma unroll
            for (int j = 0; j < 8; j++) acc[c][j] = 0.f;
        #pragma unroll 2
        for (int mid = 0; mid < RH; mid++) {
            float x[8];
            const float* xr = &sta[mid*132 + tslot*8];
            { float4 v = *(const float4*)(xr);   x[0]=v.x; x[1]=v.y; x[2]=v.z; x[3]=v.w; }
            { float4 v = *(const float4*)(xr+4); x[4]=v.x; x[5]=v.y; x[6]=v.z; x[7]=v.w; }
            float4 wv = *(const float4*)&wbs[mid*132 + coh*64 + cslot*4];
            float wc[4] = {wv.x, wv.y, wv.z, wv.w};
            #pragma unroll
            for (int c = 0; c < 4; c++)
                #pragma unroll
                for (int j = 0; j < 8; j++) acc[c][j] = fmaf(x[j], wc[c], acc[c][j]);
        }
        #pragma unroll
        for (int c = 0; c < 4; c++) {
            int co = coh*64 + cslot*4 + c;
            const float4* ip = (const float4*)(in + ((size_t)b*H + co)*T2 + t0 + tslot*8);
            float4 r0 = ip[0], r1 = ip[1];
            float4* op = (float4*)(out + ((size_t)b*H + co)*T2 + t0 + tslot*8);
            op[0] = make_float4(r0.x+acc[c][0], r0.y+acc[c][1], r0.z+acc[c][2], r0.w+acc[c][3]);
            op[1] = make_float4(r1.x+acc[c][4], r1.y+acc[c][5], r1.z+acc[c][6], r1.w+acc[c][7]);
        }
    }
}

// ---- fused relu + Wc + transpose -> z_e ----
#define Z_SH (128*136)
#define Z_SW (128*64)
__global__ void __launch_bounds__(256) zfused_k(const float* __restrict__ h, float* __restrict__ ze)
{
    extern __shared__ float s[];
    float* sh = s; float* sw = s + Z_SH;
    const int tid = threadIdx.x, tslot = tid&15, cslot = tid>>4;
    const int t0 = blockIdx.x*128, b = blockIdx.z;

    for (int idx = tid; idx < 128*128; idx += 256) {
        int ci = idx>>7, t = idx&127;
        sh[ci*136 + t] = fmaxf(h[((size_t)b*H + ci)*T2 + t0 + t], 0.f);
    }
    for (int i = tid; i < (H*DD)/4; i += 256) ((float4*)sw)[i] = ((const float4*)g_WcT)[i];
    __syncthreads();

    float acc[4][8];
    #pragma unroll
    for (int c = 0; c < 4; c++) {
        float bv = g_bc[cslot*4 + c];
        #pragma unroll
        for (int j = 0; j < 8; j++) acc[c][j] = bv;
    }
    #pragma unroll 2
    for (int ch = 0; ch < H; ch++) {
        float x[8];
        const float* xr = &sh[ch*136 + tslot*8];
        { float4 v = *(const float4*)(xr);   x[0]=v.x; x[1]=v.y; x[2]=v.z; x[3]=v.w; }
        { float4 v = *(const float4*)(xr+4); x[4]=v.x; x[5]=v.y; x[6]=v.z; x[7]=v.w; }
        float4 wv = *(const float4*)&sw[ch*64 + cslot*4];
        float wc[4] = {wv.x, wv.y, wv.z, wv.w};
        #pragma unroll
        for (int c = 0; c < 4; c++)
            #pragma unroll
            for (int j = 0; j < 8; j++) acc[c][j] = fmaf(x[j], wc[c], acc[c][j]);
    }
    #pragma unroll
    for (int j = 0; j < 8; j++) {
        size_t n = (size_t)b*T2 + t0 + tslot*8 + j;
        float2* op = (float2*)(ze + n*DD + cslot*4);
        op[0] = make_float2(acc[0][j], acc[1][j]);
        op[1] = make_float2(acc[2][j], acc[3][j]);
    }
}

// ---- VQ distance-GEMM ----
#define VQ_SZ (64*136)
#define VQ_SC (64*136)
__global__ void __launch_bounds__(256) vqgemm_k(
    const float* __restrict__ ze, const float* __restrict__ cb,
    float* __restrict__ zq, float* __restrict__ enc, float* __restrict__ idxout)
{
    extern __shared__ float s[];
    float* szeT = s; float* scb = s + VQ_SZ; float* scn = scb + VQ_SC;
    int* sbk = (int*)(scn + KCB);
    const int tid = threadIdx.x, n0 = blockIdx.x*128, nslot = tid>>4, kslot = tid&15;

    for (int idx = tid; idx < 128*DD; idx += 256) {
        int n = idx>>6, d = idx&63;
        szeT[d*136 + n] = ze[(size_t)(n0+n)*DD + d];
    }
    for (int k = tid; k < KCB; k += 256) scn[k] = g_cnorm[k];
    __syncthreads();

    float best[8]; int bk[8];
    #pragma unroll
    for (int i = 0; i < 8; i++) { best[i] = 3.4e38f; bk[i] = 0; }

    for (int kc = 0; kc < KCB; kc += 128) {
        for (int idx = tid; idx < 128*DD; idx += 256) {
            int kk = idx>>6, d = idx&63;
            scb[d*136 + kk] = cb[(size_t)(kc+kk)*DD + d];
        }
        __syncthreads();
        float acc[8][8];
        #pragma unroll
        for (int i = 0; i < 8; i++)
            #pragma unroll
            for (int j = 0; j < 8; j++) acc[i][j] = 0.f;
        #pragma unroll 2
        for (int d = 0; d < DD; d++) {
            float fz[8], fc[8];
            const float* zr = &szeT[d*136 + nslot*8];
            { float4 v = *(const float4*)(zr);   fz[0]=v.x; fz[1]=v.y; fz[2]=v.z; fz[3]=v.w; }
            { float4 v = *(const float4*)(zr+4); fz[4]=v.x; fz[5]=v.y; fz[6]=v.z; fz[7]=v.w; }
            const float* cr = &scb[d*136 + kslot*8];
            { float4 v = *(const float4*)(cr);   fc[0]=v.x; fc[1]=v.y; fc[2]=v.z; fc[3]=v.w; }
            { float4 v = *(const float4*)(cr+4); fc[4]=v.x; fc[5]=v.y; fc[6]=v.z; fc[7]=v.w; }
            #pragma unroll
            for (int i = 0; i < 8; i++)
                #pragma unroll
                for (int j = 0; j < 8; j++) acc[i][j] = fmaf(fz[i], fc[j], acc[i][j]);
        }
        #pragma unroll
        for (int j = 0; j < 8; j++) {
            int kg = kc + kslot*8 + j;
            float cn = scn[kg];
            #pragma unroll
            for (int i = 0; i < 8; i++) {
                float dist = cn - 2.f*acc[i][j];
                if (dist < best[i]) { best[i] = dist; bk[i] = kg; }
            }
        }
        __syncthreads();
    }
    #pragma unroll
    for (int off = 8; off > 0; off >>= 1) {
        #pragma unroll
        for (int i = 0; i < 8; i++) {
            float ob = __shfl_down_sync(0xffffffffu, best[i], off, 16);
            int ok = __shfl_down_sync(0xffffffffu, bk[i], off, 16);
            if (ob < best[i] || (ob == best[i] && ok < bk[i])) { best[i] = ob; bk[i] = ok; }
        }
    }
    if (kslot == 0)
        #pragma unroll
        for (int i = 0; i < 8; i++) sbk[nslot*8 + i] = bk[i];
    __syncthreads();

    float part = 0.f;
    for (int idx = tid; idx < 128*DD; idx += 256) {
        int nl = idx>>6, d = idx&63;
        int kk = sbk[nl];
        float c = cb[(size_t)kk*DD + d];
        float f = szeT[d*136 + nl];
        zq[(size_t)(n0+nl)*DD + d] = c;
        float df = c - f;
        part = fmaf(df, df, part);
    }
    const float2 z2 = make_float2(0.f, 0.f);
    for (int r = 0; r < 128; r++) ((float2*)(enc + (size_t)(n0+r)*KCB))[tid] = z2;
    __syncthreads();
    if (tid < 128) {
        int kk = sbk[tid];
        idxout[n0 + tid] = (float)kk;
        enc[(size_t)(n0+tid)*KCB + kk] = 1.f;
        atomicAdd(&g_hist[kk], 1);
    }
    #pragma unroll
    for (int o = 16; o > 0; o >>= 1) part += __shfl_down_sync(0xffffffffu, part, o);
    __shared__ float wsum[8];
    if ((tid&31) == 0) wsum[tid>>5] = part;
    __syncthreads();
    if (tid < 8) {
        float v = wsum[tid];
        #pragma unroll
        for (int o = 4; o > 0; o >>= 1) v += __shfl_down_sync(0xffu, v, o);
        if (tid == 0) atomicAdd(&g_losssum, v);
    }
}

__global__ void fin_k(float* __restrict__ loss_out, float* __restrict__ perp_out)
{
    __shared__ float red[512];
    const int k = threadIdx.x;
    float p = (float)g_hist[k]*(1.0f/(float)NN);
    red[k] = p*logf(p + 1e-10f);
    __syncthreads();
    for (int s2 = 256; s2 > 0; s2 >>= 1) { if (k < s2) red[k] += red[k + s2]; __syncthreads(); }
    if (k == 0) {
        perp_out[0] = expf(-red[0]);
        loss_out[0] = 1.25f*g_losssum/(float)((size_t)NN*DD);
    }
}

extern "C" void kernel_launch(void* const* d_in, const int* in_sizes, int n_in,
                              void* d_out, int out_size)
{
    const float* x     = (const float*)d_in[0];
    const float* w1    = (const float*)d_in[1];
    const float* b1    = (const float*)d_in[2];
    const float* w2    = (const float*)d_in[3];
    const float* b2    = (const float*)d_in[4];
    const float* w3    = (const float*)d_in[5];
    const float* b3    = (const float*)d_in[6];
    const float* r0w1  = (const float*)d_in[7];
    const float* r0w2  = (const float*)d_in[8];
    const float* r1w1  = (const float*)d_in[9];
    const float* r1w2  = (const float*)d_in[10];
    const float* w_out = (const float*)d_in[11];
    const float* b_out = (const float*)d_in[12];
    const float* wpq   = (const float*)d_in[13];
    const float* bpq   = (const float*)d_in[14];
    const float* cb    = (const float*)d_in[15];

    float* outp = (float*)d_out;
    const size_t NZ = (size_t)NN*DD;
    float* o_loss = outp;
    float* o_zq   = outp + 1;
    float* o_perp = outp + 1 + NZ;
    float* o_ze   = outp + 2 + NZ;
    float* o_enc  = outp + 2 + 2*NZ;
    float* o_idx  = outp + 2 + 2*NZ + (size_t)NN*KCB;

    auto* kConv3 = convK3_k<false, false, true>;

    const int smem_S2 = 2*(S2_WC + S2_XC)*4;        // 66,560
    const int smem_K3 = 3*(K3_WC + K3_XC)*4;        // 62,976
    const int smem_RB = (RN_STA + 2*RN_STG)*4;      // 75,776
    const int z_smem  = (Z_SH + Z_SW)*4;            // 102,400
    const int vq_smem = (VQ_SZ + VQ_SC + KCB)*4 + 128*4;

    static int attr_done = 0;
    if (!attr_done) {
        cudaFuncSetAttribute(convS2_k,   cudaFuncAttributeMaxDynamicSharedMemorySize, smem_S2);
        cudaFuncSetAttribute(kConv3,     cudaFuncAttributeMaxDynamicSharedMemorySize, smem_K3);
        cudaFuncSetAttribute(resblock_k, cudaFuncAttributeMaxDynamicSharedMemorySize, smem_RB);
        cudaFuncSetAttribute(zfused_k,   cudaFuncAttributeMaxDynamicSharedMemorySize, z_smem);
        cudaFuncSetAttribute(vqgemm_k,   cudaFuncAttributeMaxDynamicSharedMemorySize, vq_smem);
        attr_done = 1;
    }

    precompute_k<<<66, 128>>>(wpq, w_out, b_out, bpq, cb);

    convS2_k<<<dim3(16, 1, BB), 256, smem_S2>>>(x,    w1, b1, g_h1, CIN, T0, HH, T1);
    convS2_k<<<dim3(8,  2, BB), 256, smem_S2>>>(g_h1, w2, b2, g_h2, HH,  T1, H,  T2);
    kConv3<<<dim3(8, 2, BB), 256, smem_K3>>>(g_h2, w3, b3, g_h3);

    resblock_k<<<dim3(8, 1, BB), 256, smem_RB>>>(g_h3, r0w1, r0w2, g_h2);
    resblock_k<<<dim3(8, 1, BB), 256, smem_RB>>>(g_h2, r1w1, r1w2, g_h3);

    zfused_k<<<dim3(8, 1, BB), 256, z_smem>>>(g_h3, o_ze);

    vqgemm_k<<<NN/128, 256, vq_smem>>>(o_ze, cb, o_zq, o_enc, o_idx);

    fin_k<<<1, 512>>>(o_loss, o_perp);
}